// round 1
// baseline (speedup 1.0000x reference)
#include <cuda_runtime.h>
#include <cuda_bf16.h>

#define D 128
#define MAXN 100000

// Scratch for A[d] = sum_{e: dst=d} w_e * src_x[s_e]   (51.2 MB device global)
__device__ float g_A[(size_t)MAXN * D];

// ---------------------------------------------------------------------------
// Kernel 1: zero the accumulator (graph replays require re-zeroing each call)
// ---------------------------------------------------------------------------
__global__ void zero_A_kernel(int n4) {
    int i = blockIdx.x * blockDim.x + threadIdx.x;
    if (i < n4) ((float4*)g_A)[i] = make_float4(0.f, 0.f, 0.f, 0.f);
}

// ---------------------------------------------------------------------------
// Kernel 2: edge scatter. One warp per edge: gather src row, scale by w,
// 128-bit vector atomic add into A[dst].
// ---------------------------------------------------------------------------
__global__ void scatter_edges_kernel(const float* __restrict__ src_x,
                                     const int* __restrict__ ei,
                                     const float* __restrict__ ew,
                                     int E) {
    int g = blockIdx.x * blockDim.x + threadIdx.x;
    int e = g >> 5;
    int lane = g & 31;
    if (e >= E) return;
    int s = __ldg(&ei[e]);
    int d = __ldg(&ei[E + e]);
    float w = __ldg(&ew[e]);
    float4 x = __ldg((const float4*)(src_x + (size_t)s * D) + lane);
    float* p = g_A + (size_t)d * D + lane * 4;
    asm volatile("red.global.add.v4.f32 [%0], {%1,%2,%3,%4};"
                 :: "l"(p), "f"(x.x * w), "f"(x.y * w), "f"(x.z * w), "f"(x.w * w)
                 : "memory");
}

// ---------------------------------------------------------------------------
// Kernel 3: fused dual GEMM + leaky_relu.
//   out = leaky_relu( (dst_x + A) @ Wi^T + (dst_x * A) @ Wn^T )
// BM=128 rows/block, BN=128 cols, BK=16, 256 threads, TM=TN=8.
// smem staged k-major ([k][m] / [k][j]) so inner-loop fragment loads are
// contiguous float4 (conflict-free); fills do the transpose.
// ---------------------------------------------------------------------------
__global__ __launch_bounds__(256) void fused_gemm_kernel(
    const float* __restrict__ dstx,
    const float* __restrict__ Wi,
    const float* __restrict__ Wn,
    float* __restrict__ out, int N) {

    __shared__ float u_s[16][132];
    __shared__ float v_s[16][132];
    __shared__ float wi_s[16][132];
    __shared__ float wn_s[16][132];

    const int tid = threadIdx.x;
    const int tx = tid & 15;   // col group: cols tx*8 .. tx*8+7
    const int ty = tid >> 4;   // row group: rows ty*8 .. ty*8+7
    const int row0 = blockIdx.x * 128;

    float acc[8][8];
#pragma unroll
    for (int i = 0; i < 8; ++i)
#pragma unroll
        for (int j = 0; j < 8; ++j) acc[i][j] = 0.f;

    for (int kt = 0; kt < 8; ++kt) {
        const int k0 = kt * 16;
        // ---- fill: 512 float4 per matrix; 2 per thread (coalesced 32B/thread)
#pragma unroll
        for (int r = 0; r < 2; ++r) {
            int f = tid * 2 + r;        // 0..511
            int m = f >> 2;             // 0..127 (node row within block / W row j)
            int kq = (f & 3) << 2;      // 0,4,8,12 (k offset within tile)
            int row = row0 + m;
            float4 xd = make_float4(0.f, 0.f, 0.f, 0.f);
            float4 xa = make_float4(0.f, 0.f, 0.f, 0.f);
            if (row < N) {
                xd = *(const float4*)(dstx + (size_t)row * D + k0 + kq);
                xa = *(const float4*)(g_A + (size_t)row * D + k0 + kq);
            }
            u_s[kq + 0][m] = xd.x + xa.x;
            u_s[kq + 1][m] = xd.y + xa.y;
            u_s[kq + 2][m] = xd.z + xa.z;
            u_s[kq + 3][m] = xd.w + xa.w;
            v_s[kq + 0][m] = xd.x * xa.x;
            v_s[kq + 1][m] = xd.y * xa.y;
            v_s[kq + 2][m] = xd.z * xa.z;
            v_s[kq + 3][m] = xd.w * xa.w;
            float4 wiv = *(const float4*)(Wi + m * D + k0 + kq);
            float4 wnv = *(const float4*)(Wn + m * D + k0 + kq);
            wi_s[kq + 0][m] = wiv.x;
            wi_s[kq + 1][m] = wiv.y;
            wi_s[kq + 2][m] = wiv.z;
            wi_s[kq + 3][m] = wiv.w;
            wn_s[kq + 0][m] = wnv.x;
            wn_s[kq + 1][m] = wnv.y;
            wn_s[kq + 2][m] = wnv.z;
            wn_s[kq + 3][m] = wnv.w;
        }
        __syncthreads();

        // ---- inner: per k, 8 LDS.128 + 128 FMA per thread
#pragma unroll
        for (int k = 0; k < 16; ++k) {
            float4 ua = *(const float4*)&u_s[k][ty * 8];
            float4 ub = *(const float4*)&u_s[k][ty * 8 + 4];
            float4 va = *(const float4*)&v_s[k][ty * 8];
            float4 vb = *(const float4*)&v_s[k][ty * 8 + 4];
            float4 wa = *(const float4*)&wi_s[k][tx * 8];
            float4 wb = *(const float4*)&wi_s[k][tx * 8 + 4];
            float4 na = *(const float4*)&wn_s[k][tx * 8];
            float4 nb = *(const float4*)&wn_s[k][tx * 8 + 4];
            float uu[8] = {ua.x, ua.y, ua.z, ua.w, ub.x, ub.y, ub.z, ub.w};
            float vv[8] = {va.x, va.y, va.z, va.w, vb.x, vb.y, vb.z, vb.w};
            float wwi[8] = {wa.x, wa.y, wa.z, wa.w, wb.x, wb.y, wb.z, wb.w};
            float wwn[8] = {na.x, na.y, na.z, na.w, nb.x, nb.y, nb.z, nb.w};
#pragma unroll
            for (int i = 0; i < 8; ++i)
#pragma unroll
                for (int j = 0; j < 8; ++j)
                    acc[i][j] += uu[i] * wwi[j] + vv[i] * wwn[j];
        }
        __syncthreads();
    }

    // ---- epilogue: leaky_relu + coalesced float4 stores
#pragma unroll
    for (int i = 0; i < 8; ++i) {
        int row = row0 + ty * 8 + i;
        if (row < N) {
#pragma unroll
            for (int j = 0; j < 8; ++j) {
                float x = acc[i][j];
                acc[i][j] = x > 0.f ? x : 0.01f * x;
            }
            float4* op = (float4*)(out + (size_t)row * D + tx * 8);
            op[0] = make_float4(acc[i][0], acc[i][1], acc[i][2], acc[i][3]);
            op[1] = make_float4(acc[i][4], acc[i][5], acc[i][6], acc[i][7]);
        }
    }
}

// ---------------------------------------------------------------------------
extern "C" void kernel_launch(void* const* d_in, const int* in_sizes, int n_in,
                              void* d_out, int out_size) {
    const float* src_x = (const float*)d_in[0];
    const float* dst_x = (const float*)d_in[1];
    const int*   ei    = (const int*)d_in[2];    // [2, E]: src row then dst row
    const float* ew    = (const float*)d_in[3];  // [E]
    const float* Wi    = (const float*)d_in[4];  // W_intra [D, D]
    const float* Wn    = (const float*)d_in[5];  // W_inter [D, D]
    float* out = (float*)d_out;

    int N = in_sizes[0] / D;
    int E = in_sizes[2] / 2;

    int n4 = N * (D / 4);
    zero_A_kernel<<<(n4 + 255) / 256, 256>>>(n4);
    scatter_edges_kernel<<<(E + 7) / 8, 256>>>(src_x, ei, ew, E);
    fused_gemm_kernel<<<(N + 127) / 128, 256>>>(dst_x, Wi, Wn, out, N);
}

// round 2
// speedup vs baseline: 1.9486x; 1.9486x over previous
#include <cuda_runtime.h>
#include <cuda_bf16.h>
#include <cstdint>

#define D 128
#define MAXN 100000

// Scratch for A[d] = sum_{e: dst=d} w_e * src_x[s_e]   (51.2 MB device global)
__device__ float g_A[(size_t)MAXN * D];

// ---------------------------------------------------------------------------
// Kernel 1: zero the accumulator
// ---------------------------------------------------------------------------
__global__ void zero_A_kernel(int n4) {
    int i = blockIdx.x * blockDim.x + threadIdx.x;
    if (i < n4) ((float4*)g_A)[i] = make_float4(0.f, 0.f, 0.f, 0.f);
}

// ---------------------------------------------------------------------------
// Kernel 2: edge scatter. One warp per edge: gather src row, scale by w,
// 128-bit vector atomic add into A[dst].
// ---------------------------------------------------------------------------
__global__ void scatter_edges_kernel(const float* __restrict__ src_x,
                                     const int* __restrict__ ei,
                                     const float* __restrict__ ew,
                                     int E) {
    int g = blockIdx.x * blockDim.x + threadIdx.x;
    int e = g >> 5;
    int lane = g & 31;
    if (e >= E) return;
    int s = __ldg(&ei[e]);
    int d = __ldg(&ei[E + e]);
    float w = __ldg(&ew[e]);
    float4 x = __ldg((const float4*)(src_x + (size_t)s * D) + lane);
    float* p = g_A + (size_t)d * D + lane * 4;
    asm volatile("red.global.add.v4.f32 [%0], {%1,%2,%3,%4};"
                 :: "l"(p), "f"(x.x * w), "f"(x.y * w), "f"(x.z * w), "f"(x.w * w)
                 : "memory");
}

// ---------------------------------------------------------------------------
// Kernel 3: fused dual GEMM + leaky_relu on TENSOR CORES (tf32 mma.sync).
//   out = leaky_relu( (dst_x + A) @ Wi^T + (dst_x * A) @ Wn^T )
// K-concat view: [U|V] (K=256) @ [Wi|Wn]^T. BM=128, BN=128, BK=16 per array,
// 8 warps; warp tile 64x32 (4x4 m16n8k8 frags). Smem k-major, row stride 136
// floats => frag-load banks = 8*qid + grp (conflict-free).
// ---------------------------------------------------------------------------
#define SSTR 136

__device__ __forceinline__ uint32_t f2tf32(float x) {
    uint32_t r;
    asm("cvt.rna.tf32.f32 %0, %1;" : "=r"(r) : "f"(x));
    return r;
}

__device__ __forceinline__ void mma_tf32(float c[4], const uint32_t a[4],
                                         const uint32_t b[2]) {
    asm volatile(
        "mma.sync.aligned.m16n8k8.row.col.f32.tf32.tf32.f32 "
        "{%0,%1,%2,%3},{%4,%5,%6,%7},{%8,%9},{%0,%1,%2,%3};"
        : "+f"(c[0]), "+f"(c[1]), "+f"(c[2]), "+f"(c[3])
        : "r"(a[0]), "r"(a[1]), "r"(a[2]), "r"(a[3]), "r"(b[0]), "r"(b[1]));
}

__global__ __launch_bounds__(256) void fused_gemm_tc_kernel(
    const float* __restrict__ dstx,
    const float* __restrict__ Wi,
    const float* __restrict__ Wn,
    float* __restrict__ out, int N) {

    __shared__ uint32_t u_s[16][SSTR];
    __shared__ uint32_t v_s[16][SSTR];
    __shared__ uint32_t wi_s[16][SSTR];
    __shared__ uint32_t wn_s[16][SSTR];

    const int tid = threadIdx.x;
    const int lane = tid & 31;
    const int wid = tid >> 5;
    const int wm = wid >> 2;   // 0..1 : rows wm*64 .. +63
    const int wn = wid & 3;    // 0..3 : cols wn*32 .. +31
    const int grp = lane >> 2; // 0..7
    const int qid = lane & 3;  // 0..3
    const int row0 = blockIdx.x * 128;

    // fill-phase indices
    const int fm = tid >> 1;          // 0..127 (node row within tile / W out-row)
    const int fkq = (tid & 1) * 8;    // 0 or 8

    float acc[4][4][4];
#pragma unroll
    for (int mt = 0; mt < 4; ++mt)
#pragma unroll
        for (int nt = 0; nt < 4; ++nt)
#pragma unroll
            for (int c = 0; c < 4; ++c) acc[mt][nt][c] = 0.f;

    for (int kt = 0; kt < 8; ++kt) {
        const int k0 = kt * 16;

        // ---- fill u_s/v_s (nodes) and wi_s/wn_s (weights), transposed to k-major
        {
            int row = row0 + fm;
            float4 d0 = make_float4(0.f, 0.f, 0.f, 0.f), d1 = d0;
            float4 a0 = d0, a1 = d0;
            if (row < N) {
                const float4* dp = (const float4*)(dstx + (size_t)row * D + k0 + fkq);
                const float4* ap = (const float4*)(g_A + (size_t)row * D + k0 + fkq);
                d0 = dp[0]; d1 = dp[1];
                a0 = ap[0]; a1 = ap[1];
            }
            float du[8] = {d0.x, d0.y, d0.z, d0.w, d1.x, d1.y, d1.z, d1.w};
            float au[8] = {a0.x, a0.y, a0.z, a0.w, a1.x, a1.y, a1.z, a1.w};
#pragma unroll
            for (int j = 0; j < 8; ++j) {
                u_s[fkq + j][fm] = f2tf32(du[j] + au[j]);
                v_s[fkq + j][fm] = f2tf32(du[j] * au[j]);
            }
            const float4* wip = (const float4*)(Wi + fm * D + k0 + fkq);
            const float4* wnp = (const float4*)(Wn + fm * D + k0 + fkq);
            float4 wi0 = wip[0], wi1 = wip[1];
            float4 wn0 = wnp[0], wn1 = wnp[1];
            float wif[8] = {wi0.x, wi0.y, wi0.z, wi0.w, wi1.x, wi1.y, wi1.z, wi1.w};
            float wnf[8] = {wn0.x, wn0.y, wn0.z, wn0.w, wn1.x, wn1.y, wn1.z, wn1.w};
#pragma unroll
            for (int j = 0; j < 8; ++j) {
                wi_s[fkq + j][fm] = f2tf32(wif[j]);
                wn_s[fkq + j][fm] = f2tf32(wnf[j]);
            }
        }
        __syncthreads();

        // ---- compute: 2 phases (u*Wi, v*Wn) x 2 k8-steps
#pragma unroll
        for (int ph = 0; ph < 2; ++ph) {
            const uint32_t(*S)[SSTR] = ph ? v_s : u_s;
            const uint32_t(*W)[SSTR] = ph ? wn_s : wi_s;
#pragma unroll
            for (int kk = 0; kk < 16; kk += 8) {
                uint32_t af[4][4];
#pragma unroll
                for (int mt = 0; mt < 4; ++mt) {
                    int mr = wm * 64 + mt * 16 + grp;
                    af[mt][0] = S[kk + qid][mr];
                    af[mt][1] = S[kk + qid][mr + 8];
                    af[mt][2] = S[kk + qid + 4][mr];
                    af[mt][3] = S[kk + qid + 4][mr + 8];
                }
                uint32_t bf[4][2];
#pragma unroll
                for (int nt = 0; nt < 4; ++nt) {
                    int nc = wn * 32 + nt * 8 + grp;
                    bf[nt][0] = W[kk + qid][nc];
                    bf[nt][1] = W[kk + qid + 4][nc];
                }
#pragma unroll
                for (int mt = 0; mt < 4; ++mt)
#pragma unroll
                    for (int nt = 0; nt < 4; ++nt)
                        mma_tf32(acc[mt][nt], af[mt], bf[nt]);
            }
        }
        __syncthreads();
    }

    // ---- epilogue: leaky_relu + float2 stores
#pragma unroll
    for (int mt = 0; mt < 4; ++mt) {
#pragma unroll
        for (int nt = 0; nt < 4; ++nt) {
            int col = wn * 32 + nt * 8 + qid * 2;
            int r0 = row0 + wm * 64 + mt * 16 + grp;
            int r1 = r0 + 8;
            float x0 = acc[mt][nt][0], x1 = acc[mt][nt][1];
            float x2 = acc[mt][nt][2], x3 = acc[mt][nt][3];
            x0 = x0 > 0.f ? x0 : 0.01f * x0;
            x1 = x1 > 0.f ? x1 : 0.01f * x1;
            x2 = x2 > 0.f ? x2 : 0.01f * x2;
            x3 = x3 > 0.f ? x3 : 0.01f * x3;
            if (r0 < N)
                *(float2*)(out + (size_t)r0 * D + col) = make_float2(x0, x1);
            if (r1 < N)
                *(float2*)(out + (size_t)r1 * D + col) = make_float2(x2, x3);
        }
    }
}

// ---------------------------------------------------------------------------
extern "C" void kernel_launch(void* const* d_in, const int* in_sizes, int n_in,
                              void* d_out, int out_size) {
    const float* src_x = (const float*)d_in[0];
    const float* dst_x = (const float*)d_in[1];
    const int*   ei    = (const int*)d_in[2];    // [2, E]
    const float* ew    = (const float*)d_in[3];  // [E]
    const float* Wi    = (const float*)d_in[4];  // W_intra [D, D]
    const float* Wn    = (const float*)d_in[5];  // W_inter [D, D]
    float* out = (float*)d_out;

    int N = in_sizes[0] / D;
    int E = in_sizes[2] / 2;

    int n4 = N * (D / 4);
    zero_A_kernel<<<(n4 + 255) / 256, 256>>>(n4);
    scatter_edges_kernel<<<(E + 7) / 8, 256>>>(src_x, ei, ew, E);
    fused_gemm_tc_kernel<<<(N + 127) / 128, 256>>>(dst_x, Wi, Wn, out, N);
}

// round 3
// speedup vs baseline: 2.2889x; 1.1747x over previous
#include <cuda_runtime.h>
#include <cuda_bf16.h>
#include <cstdint>

#define D 128
#define MAXN 100000
#define MAXE 600000
#define SCAN_NB ((MAXN + 255) / 256)   // 391

// Scratch (device globals; no allocs allowed)
__device__ float g_A[(size_t)MAXN * D];     // 51.2 MB
__device__ int   g_count[MAXN];
__device__ int   g_offs[MAXN];
__device__ int   g_cursor[MAXN];
__device__ int   g_bsum[SCAN_NB + 1];
__device__ int   g_perm[MAXE];

// ---------------------------------------------------------------------------
// Counting sort of edges by dst
// ---------------------------------------------------------------------------
__global__ void zero_count_kernel(int N) {
    int i = blockIdx.x * blockDim.x + threadIdx.x;
    if (i < N) g_count[i] = 0;
}

__global__ void hist_kernel(const int* __restrict__ ei, int E) {
    int e = blockIdx.x * blockDim.x + threadIdx.x;
    if (e < E) atomicAdd(&g_count[ei[E + e]], 1);
}

// s1: per-256-block inclusive scan; write exclusive offs + block total
__global__ void scan1_kernel(int N) {
    __shared__ int s[256];
    int i = blockIdx.x * 256 + threadIdx.x;
    int c = (i < N) ? g_count[i] : 0;
    s[threadIdx.x] = c;
    __syncthreads();
#pragma unroll
    for (int o = 1; o < 256; o <<= 1) {
        int t = (threadIdx.x >= o) ? s[threadIdx.x - o] : 0;
        __syncthreads();
        s[threadIdx.x] += t;
        __syncthreads();
    }
    if (i < N) g_offs[i] = s[threadIdx.x] - c;
    if (threadIdx.x == 255) g_bsum[blockIdx.x] = s[255];
}

// s2: single block exclusive scan over block sums
__global__ void scan2_kernel(int nb) {
    __shared__ int s[512];
    int c = (threadIdx.x < nb) ? g_bsum[threadIdx.x] : 0;
    s[threadIdx.x] = c;
    __syncthreads();
#pragma unroll
    for (int o = 1; o < 512; o <<= 1) {
        int t = (threadIdx.x >= o) ? s[threadIdx.x - o] : 0;
        __syncthreads();
        s[threadIdx.x] += t;
        __syncthreads();
    }
    if (threadIdx.x < nb) g_bsum[threadIdx.x] = s[threadIdx.x] - c;  // exclusive
}

// s3: add block offsets; init cursors
__global__ void scan3_kernel(int N) {
    int i = blockIdx.x * 256 + threadIdx.x;
    if (i < N) {
        int v = g_offs[i] + g_bsum[i >> 8];
        g_offs[i] = v;
        g_cursor[i] = v;
    }
}

__global__ void permute_kernel(const int* __restrict__ ei, int E) {
    int e = blockIdx.x * blockDim.x + threadIdx.x;
    if (e < E) {
        int pos = atomicAdd(&g_cursor[ei[E + e]], 1);
        g_perm[pos] = e;
    }
}

// ---------------------------------------------------------------------------
// Gather: one warp per dst node; accumulate w*src_x[s] over its edge segment
// in registers, single plain store of A[d]. No atomics on A, no zero pass.
// ---------------------------------------------------------------------------
__global__ __launch_bounds__(256) void gather_kernel(
    const float* __restrict__ src_x,
    const int* __restrict__ ei,
    const float* __restrict__ ew,
    int N, int E) {
    int w = (blockIdx.x * 256 + threadIdx.x) >> 5;
    int lane = threadIdx.x & 31;
    if (w >= N) return;
    int base = g_offs[w];
    int deg = g_count[w];
    float4 acc = make_float4(0.f, 0.f, 0.f, 0.f);
    int i = 0;
    // prefetch-unrolled by 2 for MLP
    for (; i + 2 <= deg; i += 2) {
        int e0 = __ldg(&g_perm[base + i]);
        int e1 = __ldg(&g_perm[base + i + 1]);
        int s0 = __ldg(&ei[e0]);
        int s1 = __ldg(&ei[e1]);
        float w0 = __ldg(&ew[e0]);
        float w1 = __ldg(&ew[e1]);
        float4 x0 = __ldg((const float4*)(src_x + (size_t)s0 * D) + lane);
        float4 x1 = __ldg((const float4*)(src_x + (size_t)s1 * D) + lane);
        acc.x += w0 * x0.x + w1 * x1.x;
        acc.y += w0 * x0.y + w1 * x1.y;
        acc.z += w0 * x0.z + w1 * x1.z;
        acc.w += w0 * x0.w + w1 * x1.w;
    }
    for (; i < deg; ++i) {
        int e0 = __ldg(&g_perm[base + i]);
        int s0 = __ldg(&ei[e0]);
        float w0 = __ldg(&ew[e0]);
        float4 x0 = __ldg((const float4*)(src_x + (size_t)s0 * D) + lane);
        acc.x += w0 * x0.x;
        acc.y += w0 * x0.y;
        acc.z += w0 * x0.z;
        acc.w += w0 * x0.w;
    }
    ((float4*)(g_A + (size_t)w * D))[lane] = acc;
}

// ---------------------------------------------------------------------------
// Fused dual GEMM + leaky_relu on tensor cores (tf32 mma.sync) — unchanged.
//   out = leaky_relu( (dst_x + A) @ Wi^T + (dst_x * A) @ Wn^T )
// ---------------------------------------------------------------------------
#define SSTR 136

__device__ __forceinline__ uint32_t f2tf32(float x) {
    uint32_t r;
    asm("cvt.rna.tf32.f32 %0, %1;" : "=r"(r) : "f"(x));
    return r;
}

__device__ __forceinline__ void mma_tf32(float c[4], const uint32_t a[4],
                                         const uint32_t b[2]) {
    asm volatile(
        "mma.sync.aligned.m16n8k8.row.col.f32.tf32.tf32.f32 "
        "{%0,%1,%2,%3},{%4,%5,%6,%7},{%8,%9},{%0,%1,%2,%3};"
        : "+f"(c[0]), "+f"(c[1]), "+f"(c[2]), "+f"(c[3])
        : "r"(a[0]), "r"(a[1]), "r"(a[2]), "r"(a[3]), "r"(b[0]), "r"(b[1]));
}

__global__ __launch_bounds__(256) void fused_gemm_tc_kernel(
    const float* __restrict__ dstx,
    const float* __restrict__ Wi,
    const float* __restrict__ Wn,
    float* __restrict__ out, int N) {

    __shared__ uint32_t u_s[16][SSTR];
    __shared__ uint32_t v_s[16][SSTR];
    __shared__ uint32_t wi_s[16][SSTR];
    __shared__ uint32_t wn_s[16][SSTR];

    const int tid = threadIdx.x;
    const int lane = tid & 31;
    const int wid = tid >> 5;
    const int wm = wid >> 2;
    const int wn = wid & 3;
    const int grp = lane >> 2;
    const int qid = lane & 3;
    const int row0 = blockIdx.x * 128;

    const int fm = tid >> 1;
    const int fkq = (tid & 1) * 8;

    float acc[4][4][4];
#pragma unroll
    for (int mt = 0; mt < 4; ++mt)
#pragma unroll
        for (int nt = 0; nt < 4; ++nt)
#pragma unroll
            for (int c = 0; c < 4; ++c) acc[mt][nt][c] = 0.f;

    for (int kt = 0; kt < 8; ++kt) {
        const int k0 = kt * 16;
        {
            int row = row0 + fm;
            float4 d0 = make_float4(0.f, 0.f, 0.f, 0.f), d1 = d0;
            float4 a0 = d0, a1 = d0;
            if (row < N) {
                const float4* dp = (const float4*)(dstx + (size_t)row * D + k0 + fkq);
                const float4* ap = (const float4*)(g_A + (size_t)row * D + k0 + fkq);
                d0 = dp[0]; d1 = dp[1];
                a0 = ap[0]; a1 = ap[1];
            }
            float du[8] = {d0.x, d0.y, d0.z, d0.w, d1.x, d1.y, d1.z, d1.w};
            float au[8] = {a0.x, a0.y, a0.z, a0.w, a1.x, a1.y, a1.z, a1.w};
#pragma unroll
            for (int j = 0; j < 8; ++j) {
                u_s[fkq + j][fm] = f2tf32(du[j] + au[j]);
                v_s[fkq + j][fm] = f2tf32(du[j] * au[j]);
            }
            const float4* wip = (const float4*)(Wi + fm * D + k0 + fkq);
            const float4* wnp = (const float4*)(Wn + fm * D + k0 + fkq);
            float4 wi0 = wip[0], wi1 = wip[1];
            float4 wn0 = wnp[0], wn1 = wnp[1];
            float wif[8] = {wi0.x, wi0.y, wi0.z, wi0.w, wi1.x, wi1.y, wi1.z, wi1.w};
            float wnf[8] = {wn0.x, wn0.y, wn0.z, wn0.w, wn1.x, wn1.y, wn1.z, wn1.w};
#pragma unroll
            for (int j = 0; j < 8; ++j) {
                wi_s[fkq + j][fm] = f2tf32(wif[j]);
                wn_s[fkq + j][fm] = f2tf32(wnf[j]);
            }
        }
        __syncthreads();

#pragma unroll
        for (int ph = 0; ph < 2; ++ph) {
            const uint32_t(*S)[SSTR] = ph ? v_s : u_s;
            const uint32_t(*W)[SSTR] = ph ? wn_s : wi_s;
#pragma unroll
            for (int kk = 0; kk < 16; kk += 8) {
                uint32_t af[4][4];
#pragma unroll
                for (int mt = 0; mt < 4; ++mt) {
                    int mr = wm * 64 + mt * 16 + grp;
                    af[mt][0] = S[kk + qid][mr];
                    af[mt][1] = S[kk + qid][mr + 8];
                    af[mt][2] = S[kk + qid + 4][mr];
                    af[mt][3] = S[kk + qid + 4][mr + 8];
                }
                uint32_t bf[4][2];
#pragma unroll
                for (int nt = 0; nt < 4; ++nt) {
                    int nc = wn * 32 + nt * 8 + grp;
                    bf[nt][0] = W[kk + qid][nc];
                    bf[nt][1] = W[kk + qid + 4][nc];
                }
#pragma unroll
                for (int mt = 0; mt < 4; ++mt)
#pragma unroll
                    for (int nt = 0; nt < 4; ++nt)
                        mma_tf32(acc[mt][nt], af[mt], bf[nt]);
            }
        }
        __syncthreads();
    }

#pragma unroll
    for (int mt = 0; mt < 4; ++mt) {
#pragma unroll
        for (int nt = 0; nt < 4; ++nt) {
            int col = wn * 32 + nt * 8 + qid * 2;
            int r0 = row0 + wm * 64 + mt * 16 + grp;
            int r1 = r0 + 8;
            float x0 = acc[mt][nt][0], x1 = acc[mt][nt][1];
            float x2 = acc[mt][nt][2], x3 = acc[mt][nt][3];
            x0 = x0 > 0.f ? x0 : 0.01f * x0;
            x1 = x1 > 0.f ? x1 : 0.01f * x1;
            x2 = x2 > 0.f ? x2 : 0.01f * x2;
            x3 = x3 > 0.f ? x3 : 0.01f * x3;
            if (r0 < N)
                *(float2*)(out + (size_t)r0 * D + col) = make_float2(x0, x1);
            if (r1 < N)
                *(float2*)(out + (size_t)r1 * D + col) = make_float2(x2, x3);
        }
    }
}

// ---------------------------------------------------------------------------
extern "C" void kernel_launch(void* const* d_in, const int* in_sizes, int n_in,
                              void* d_out, int out_size) {
    const float* src_x = (const float*)d_in[0];
    const float* dst_x = (const float*)d_in[1];
    const int*   ei    = (const int*)d_in[2];    // [2, E]
    const float* ew    = (const float*)d_in[3];  // [E]
    const float* Wi    = (const float*)d_in[4];
    const float* Wn    = (const float*)d_in[5];
    float* out = (float*)d_out;

    int N = in_sizes[0] / D;
    int E = in_sizes[2] / 2;
    int nb = (N + 255) / 256;

    zero_count_kernel<<<nb, 256>>>(N);
    hist_kernel<<<(E + 255) / 256, 256>>>(ei, E);
    scan1_kernel<<<nb, 256>>>(N);
    scan2_kernel<<<1, 512>>>(nb);
    scan3_kernel<<<nb, 256>>>(N);
    permute_kernel<<<(E + 255) / 256, 256>>>(ei, E);
    gather_kernel<<<(N * 32 + 255) / 256, 256>>>(src_x, ei, ew, N, E);
    fused_gemm_tc_kernel<<<(N + 127) / 128, 256>>>(dst_x, Wi, Wn, out, N);
}